// round 1
// baseline (speedup 1.0000x reference)
#include <cuda_runtime.h>
#include <math.h>

#define U_CNT 30000
#define I_CNT 60000
#define G_CNT 2000
#define EMBD  64
#define N_UI  (U_CNT + I_CNT)      // 90000
#define N_TOT (N_UI + G_CNT)       // 92000

// ---------------- device scratch (static, no allocation) ----------------
__device__ float g_cur [N_UI * EMBD];   // current node embeddings (user then item)
__device__ float g_msgu[G_CNT * EMBD];
__device__ float g_msgi[G_CNT * EMBD];
__device__ float g_msg [G_CNT * EMBD];

// ---------------- init: cur = concat(user,item); out = [cur ; group_emb] ----------------
__global__ void init_kernel(const float* __restrict__ ue,
                            const float* __restrict__ ie,
                            const float* __restrict__ ge,
                            float* __restrict__ out,
                            float* __restrict__ cur)
{
    int i = blockIdx.x * blockDim.x + threadIdx.x;
    const int totUI = N_UI * EMBD;
    if (i < totUI) {
        float v = (i < U_CNT * EMBD) ? ue[i] : ie[i - U_CNT * EMBD];
        cur[i] = v;
        out[i] = v;
    } else if (i < totUI + G_CNT * EMBD) {
        out[i] = ge[i - totUI];
    }
}

__global__ void zero_msgs(float* __restrict__ mu, float* __restrict__ mi)
{
    int i = blockIdx.x * blockDim.x + threadIdx.x;
    if (i < G_CNT * EMBD) { mu[i] = 0.f; mi[i] = 0.f; }
}

// ---------------- fp32 tiled GEMM, C[M,64] = A[M,K] @ B[K,64] ----------------
// BM=64, BN=64, BK=32, 256 threads, 4x4 microtile.
// ATOMIC=true : split-K partials accumulated with atomicAdd into C (C pre-zeroed).
// ATOMIC=false: full-K per block; C[idx]=acc and outAdd[idx]+=acc (fused epilogue).
template <bool ATOMIC>
__global__ __launch_bounds__(256)
void gemm_n64(const float* __restrict__ A, const float* __restrict__ B,
              float* __restrict__ C, float* __restrict__ outAdd,
              int M, int K, int kChunk)
{
    __shared__ float As[32][68];   // k-major, padded (float4-aligned, 4-way store conflict ok)
    __shared__ float Bs[32][64];

    const int m0   = blockIdx.x * 64;
    const int k0   = blockIdx.y * kChunk;
    const int kEnd = min(k0 + kChunk, K);

    const int tid = threadIdx.x;
    const int tx  = tid & 15;     // 0..15 -> 4 cols each
    const int ty  = tid >> 4;     // 0..15 -> 4 rows each

    float acc[4][4];
#pragma unroll
    for (int i = 0; i < 4; i++)
#pragma unroll
        for (int j = 0; j < 4; j++) acc[i][j] = 0.f;

    for (int kb = k0; kb < kEnd; kb += 32) {
        // load A tile (64 rows x 32 k) transposed into As[k][m]
        {
            const int c  = tid & 31;     // k within tile
            const int r0 = tid >> 5;     // 0..7
            const int kg = kb + c;
            const bool kok = (kg < kEnd);
#pragma unroll
            for (int i = 0; i < 8; i++) {
                int r = r0 + i * 8;
                int m = m0 + r;
                float v = 0.f;
                if (kok && m < M) v = A[(size_t)m * K + kg];
                As[c][r] = v;
            }
        }
        // load B tile (32 k x 64 n)
        {
            const int n  = tid & 63;
            const int r0 = tid >> 6;     // 0..3
#pragma unroll
            for (int i = 0; i < 8; i++) {
                int r  = r0 + i * 4;
                int kg = kb + r;
                float v = 0.f;
                if (kg < kEnd) v = B[(size_t)kg * 64 + n];
                Bs[r][n] = v;
            }
        }
        __syncthreads();

#pragma unroll
        for (int kk = 0; kk < 32; kk++) {
            float4 a = *(const float4*)&As[kk][ty * 4];
            float4 b = *(const float4*)&Bs[kk][tx * 4];
            float av[4] = {a.x, a.y, a.z, a.w};
            float bv[4] = {b.x, b.y, b.z, b.w};
#pragma unroll
            for (int i = 0; i < 4; i++)
#pragma unroll
                for (int j = 0; j < 4; j++)
                    acc[i][j] = fmaf(av[i], bv[j], acc[i][j]);
        }
        __syncthreads();
    }

#pragma unroll
    for (int i = 0; i < 4; i++) {
        int m = m0 + ty * 4 + i;
        if (m < M) {
#pragma unroll
            for (int j = 0; j < 4; j++) {
                int idx = m * 64 + tx * 4 + j;
                if (ATOMIC) {
                    atomicAdd(&C[idx], acc[i][j]);
                } else {
                    C[idx] = acc[i][j];
                    outAdd[idx] += acc[i][j];
                }
            }
        }
    }
}

// ---------------- per-group attention + MLP fusion ----------------
// 256 threads = 4 groups x 64 lanes. Computes msg[g] and out_he[g] += msg[g].
__global__ __launch_bounds__(256)
void group_kernel(const float* __restrict__ mu, const float* __restrict__ mi,
                  const float* __restrict__ gemb,
                  const float* __restrict__ qc_w1, const float* __restrict__ qc_b1,
                  const float* __restrict__ qc_w2,
                  const float* __restrict__ user_w, const float* __restrict__ user_b,
                  const float* __restrict__ item_w, const float* __restrict__ item_b,
                  float* __restrict__ msg, float* __restrict__ out)
{
    const int sub = threadIdx.x >> 6;   // 0..3
    const int j   = threadIdx.x & 63;
    const int g   = blockIdx.x * 4 + sub;   // G=2000 divisible by 4

    __shared__ float xu[4][64], xi[4][64], ge[4][64];
    __shared__ float tu[4][64], ti[4][64];
    __shared__ float du[4][64], di[4][64];
    __shared__ float redA[4][64], redB[4][64];

    xu[sub][j] = mu[g * 64 + j];
    xi[sub][j] = mi[g * 64 + j];
    ge[sub][j] = gemb[g * 64 + j];
    __syncthreads();

    // t = tanh(x @ W1 + b1)
    {
        float hu = qc_b1[j], hi = qc_b1[j];
#pragma unroll 8
        for (int k = 0; k < 64; k++) {
            float w = qc_w1[k * 64 + j];
            hu = fmaf(xu[sub][k], w, hu);
            hi = fmaf(xi[sub][k], w, hi);
        }
        tu[sub][j] = tanhf(hu);
        ti[sub][j] = tanhf(hi);
    }
    __syncthreads();

    // q = t @ w2  (scalar per group), tree reduction over 64 lanes
    {
        float w2 = qc_w2[j];
        redA[sub][j] = tu[sub][j] * w2;
        redB[sub][j] = ti[sub][j] * w2;
    }
    __syncthreads();
    for (int s = 32; s > 0; s >>= 1) {
        if (j < s) {
            redA[sub][j] += redA[sub][j + s];
            redB[sub][j] += redB[sub][j + s];
        }
        __syncthreads();
    }
    const float qu = redA[sub][0];
    const float qi = redB[sub][0];

    // softmax over [qu, qi]
    const float mx = fmaxf(qu, qi);
    const float eu = expf(qu - mx);
    const float ei = expf(qi - mx);
    const float w0 = eu / (eu + ei);
    const float w1v = ei / (eu + ei);

    const float c = w0 * xu[sub][j] + w1v * xi[sub][j];
    du[sub][j] = xu[sub][j] - c;
    di[sub][j] = xi[sub][j] - c;
    __syncthreads();

    // u2 = [du ; ge] @ user_w + user_b ; i2 = [di ; ge] @ item_w + item_b
    float u2 = user_b[j];
    float i2 = item_b[j];
#pragma unroll 8
    for (int k = 0; k < 64; k++) {
        u2 = fmaf(du[sub][k], user_w[k * 64 + j], u2);
        i2 = fmaf(di[sub][k], item_w[k * 64 + j], i2);
    }
#pragma unroll 8
    for (int k = 0; k < 64; k++) {
        float gv = ge[sub][k];
        u2 = fmaf(gv, user_w[(64 + k) * 64 + j], u2);
        i2 = fmaf(gv, item_w[(64 + k) * 64 + j], i2);
    }

    const float m = u2 + i2 + c;
    msg[g * 64 + j] = m;
    out[N_UI * 64 + g * 64 + j] += m;   // final_he accumulation
}

// ---------------- launch ----------------
extern "C" void kernel_launch(void* const* d_in, const int* in_sizes, int n_in,
                              void* d_out, int out_size)
{
    const float* user_emb   = (const float*)d_in[0];
    const float* item_emb   = (const float*)d_in[1];
    const float* group_emb  = (const float*)d_in[2];
    const float* user_hyper = (const float*)d_in[3];
    const float* item_hyper = (const float*)d_in[4];
    const float* full_hyper = (const float*)d_in[5];

    // num_users / num_items may or may not be materialized as inputs
    int wbase = 6;
    if (n_in >= 15 && in_sizes[6] == 1 && in_sizes[7] == 1) wbase = 8;
    const float* qc_w1  = (const float*)d_in[wbase + 0];  // [2,64,64]
    const float* qc_b1  = (const float*)d_in[wbase + 1];  // [2,64]
    const float* qc_w2  = (const float*)d_in[wbase + 2];  // [2,64,1]
    const float* user_w = (const float*)d_in[wbase + 3];  // [2,128,64]
    const float* user_b = (const float*)d_in[wbase + 4];  // [2,64]
    const float* item_w = (const float*)d_in[wbase + 5];  // [2,128,64]
    const float* item_b = (const float*)d_in[wbase + 6];  // [2,64]

    float* out = (float*)d_out;

    float *cur, *mu, *mi, *mg;
    cudaGetSymbolAddress((void**)&cur, g_cur);
    cudaGetSymbolAddress((void**)&mu,  g_msgu);
    cudaGetSymbolAddress((void**)&mi,  g_msgi);
    cudaGetSymbolAddress((void**)&mg,  g_msg);

    init_kernel<<<(N_TOT * EMBD + 255) / 256, 256>>>(user_emb, item_emb, group_emb, out, cur);

    const int KC = 1024;
    for (int l = 0; l < 2; l++) {
        zero_msgs<<<(G_CNT * EMBD + 255) / 256, 256>>>(mu, mi);

        // msg_u = user_hyper @ cur[:U]
        {
            dim3 grid((G_CNT + 63) / 64, (U_CNT + KC - 1) / KC);
            gemm_n64<true><<<grid, 256>>>(user_hyper, cur, mu, nullptr,
                                          G_CNT, U_CNT, KC);
        }
        // msg_i = item_hyper @ cur[U:]
        {
            dim3 grid((G_CNT + 63) / 64, (I_CNT + KC - 1) / KC);
            gemm_n64<true><<<grid, 256>>>(item_hyper, cur + (size_t)U_CNT * EMBD, mi, nullptr,
                                          G_CNT, I_CNT, KC);
        }
        // attention + MLPs -> msg ; out_he += msg
        group_kernel<<<G_CNT / 4, 256>>>(mu, mi, group_emb,
                                         qc_w1 + l * 64 * 64, qc_b1 + l * 64,
                                         qc_w2 + l * 64,
                                         user_w + l * 128 * 64, user_b + l * 64,
                                         item_w + l * 128 * 64, item_b + l * 64,
                                         mg, out);
        // cur = full_hyper @ msg ; out[:90000*64] += cur
        {
            dim3 grid((N_UI + 63) / 64, 1);
            gemm_n64<false><<<grid, 256>>>(full_hyper, mg, cur, out,
                                           N_UI, G_CNT, G_CNT);
        }
    }
    (void)in_sizes; (void)n_in; (void)out_size;
}